// round 12
// baseline (speedup 1.0000x reference)
#include <cuda_runtime.h>
#include <cuda_fp16.h>

#define EMB 32
#define K 10
#define APITCH 72   // halves per A row (144B): ldmatrix conflict-free

// fp16 tables (device globals: allocation-free scratch)
__device__ __align__(16) __half g_embh[500000 * EMB];   // 32 MB
__device__ __align__(16) __half g_h1h [500000 * EMB];   // 32 MB

// unpack 8 halves (one uint4) -> 8 floats
__device__ __forceinline__ void cvt8(uint4 v, float* f)
{
    const __half2* h = reinterpret_cast<const __half2*>(&v);
    #pragma unroll
    for (int i = 0; i < 4; i++) {
        float2 t = __half22float2(h[i]);
        f[2 * i]     = t.x;
        f[2 * i + 1] = t.y;
    }
}

// ---- fp32 -> fp16 conversion, 2 independent uint4 outputs per iter ----
__global__ __launch_bounds__(256)
void cvt_f32_to_f16(const float4* __restrict__ src, uint4* __restrict__ dst, int n8)
{
    int i = blockIdx.x * blockDim.x + threadIdx.x;
    int stride = gridDim.x * blockDim.x;
    for (; i + stride < n8; i += 2 * stride) {
        int j = i + stride;
        float4 a0 = src[2 * i],  b0 = src[2 * i + 1];
        float4 a1 = src[2 * j],  b1 = src[2 * j + 1];
        __half2 h0[4], h1[4];
        h0[0] = __floats2half2_rn(a0.x, a0.y); h0[1] = __floats2half2_rn(a0.z, a0.w);
        h0[2] = __floats2half2_rn(b0.x, b0.y); h0[3] = __floats2half2_rn(b0.z, b0.w);
        h1[0] = __floats2half2_rn(a1.x, a1.y); h1[1] = __floats2half2_rn(a1.z, a1.w);
        h1[2] = __floats2half2_rn(b1.x, b1.y); h1[3] = __floats2half2_rn(b1.z, b1.w);
        dst[i] = *reinterpret_cast<const uint4*>(h0);
        dst[j] = *reinterpret_cast<const uint4*>(h1);
    }
    // tail
    for (; i < n8; i += stride) {
        float4 a = src[2 * i], b = src[2 * i + 1];
        __half2 h[4];
        h[0] = __floats2half2_rn(a.x, a.y); h[1] = __floats2half2_rn(a.z, a.w);
        h[2] = __floats2half2_rn(b.x, b.y); h[3] = __floats2half2_rn(b.z, b.w);
        dst[i] = *reinterpret_cast<const uint4*>(h);
    }
}

// ======================================================================
// FUSED layer kernel with smem-staged neighbor ids.
// per warp D[32,32] = relu([self|agg(mean)] @ W^T) via HMMA m16n8k16
// ======================================================================
__device__ __forceinline__ void mma16816(float* c, const unsigned* a,
                                         unsigned b0, unsigned b1)
{
    asm volatile(
        "mma.sync.aligned.m16n8k16.row.col.f32.f16.f16.f32 "
        "{%0,%1,%2,%3}, {%4,%5,%6,%7}, {%8,%9}, {%0,%1,%2,%3};"
        : "+f"(c[0]), "+f"(c[1]), "+f"(c[2]), "+f"(c[3])
        : "r"(a[0]), "r"(a[1]), "r"(a[2]), "r"(a[3]), "r"(b0), "r"(b1));
}

template<bool SELF_GATHER, bool OUT_HALF>
__global__ __launch_bounds__(128, 6)
void sage_fused_kernel(const __half* __restrict__ feat,      // [*, 32] fp16
                       const int*    __restrict__ node_ids,  // if SELF_GATHER
                       const int*    __restrict__ neigh,     // [N_NODES, K]
                       const float*  __restrict__ W,         // [32 out, 64 in]
                       void*         __restrict__ outp,
                       int n)
{
    __shared__ __align__(16) __half As[128 * APITCH];   // 18.4 KB
    __shared__ int ssid[128];                            // 0.5 KB
    __shared__ int snb[128 * K];                         // 5 KB

    const int tid   = threadIdx.x;
    const int lane  = tid & 31;
    const int wrp   = tid >> 5;
    const int g     = lane >> 2;      // group 0..7 (one node per pass)
    const int tig   = lane & 3;       // 16B chunk within 64B row
    const int bbase = blockIdx.x * 128;
    const int nbase = bbase + wrp * 32;

    // ---- STAGE ids into smem (once per block) ----
    {
        int t  = bbase + tid;
        int tc = min(t, n - 1);
        int s  = SELF_GATHER ? node_ids[tc] : tc;
        ssid[tid] = s;
        if (SELF_GATHER) {
            // scattered: each thread fetches its own node's K ids (independent)
            #pragma unroll
            for (int k = 0; k < K; k++)
                snb[tid * K + k] = neigh[s * K + k];
        } else {
            // identity: 128 consecutive neigh rows -> fully coalesced
            #pragma unroll
            for (int x = tid; x < 128 * K; x += 128) {
                int t2 = bbase + x / K;
                // clamp only matters in the last partial block
                snb[x] = neigh[min(t2, n - 1) * K + (x % K)];
            }
        }
    }
    __syncthreads();

    // ---- PHASE A: gather self + mean(neigh) straight into As ----
    #pragma unroll
    for (int p = 0; p < 4; p++) {
        int r   = p * 8 + g;
        int row = wrp * 32 + r;          // block-local node index
        int sid = ssid[row];

        // self row chunk
        uint4 vs = *(reinterpret_cast<const uint4*>(feat + (size_t)sid * EMB) + tig);

        // 10 independent LDG.128 in flight (ids from smem: 29-cyc chain)
        uint4 raw[K];
        #pragma unroll
        for (int k = 0; k < K; k++)
            raw[k] = *(reinterpret_cast<const uint4*>(
                           feat + (size_t)snb[row * K + k] * EMB) + tig);

        float acc[8] = {0,0,0,0,0,0,0,0};
        #pragma unroll
        for (int k = 0; k < K; k++) {
            float f[8];
            cvt8(raw[k], f);
            #pragma unroll
            for (int i = 0; i < 8; i++) acc[i] += f[i];
        }

        __half2 h[4];
        #pragma unroll
        for (int i = 0; i < 4; i++)
            h[i] = __floats2half2_rn(acc[2 * i] * 0.1f, acc[2 * i + 1] * 0.1f);

        __half* dst = &As[row * APITCH];
        *reinterpret_cast<uint4*>(dst + tig * 8)      = vs;                          // self
        *reinterpret_cast<uint4*>(dst + 32 + tig * 8) = *reinterpret_cast<const uint4*>(h); // agg
    }
    __syncwarp();

    // ---- PHASE B: B fragments (fp32 W -> fp16) ----
    unsigned b[4][4][2];
    #pragma unroll
    for (int kt = 0; kt < 4; kt++) {
        #pragma unroll
        for (int nt = 0; nt < 4; nt++) {
            int nrow = nt * 8 + g;
            int k0   = kt * 16 + tig * 2;
            float2 w0 = *reinterpret_cast<const float2*>(W + nrow * 64 + k0);
            float2 w1 = *reinterpret_cast<const float2*>(W + nrow * 64 + k0 + 8);
            __half2 h0 = __floats2half2_rn(w0.x, w0.y);
            __half2 h1 = __floats2half2_rn(w1.x, w1.y);
            b[kt][nt][0] = *reinterpret_cast<unsigned*>(&h0);
            b[kt][nt][1] = *reinterpret_cast<unsigned*>(&h1);
        }
    }

    // ---- PHASE C: mma mainloop (2 m-tiles x 4 n-tiles x 4 k-tiles) ----
    float acc[2][4][4];
    #pragma unroll
    for (int mt = 0; mt < 2; mt++)
        #pragma unroll
        for (int nt = 0; nt < 4; nt++)
            #pragma unroll
            for (int q = 0; q < 4; q++) acc[mt][nt][q] = 0.f;

    #pragma unroll
    for (int kt = 0; kt < 4; kt++) {
        #pragma unroll
        for (int mt = 0; mt < 2; mt++) {
            int row  = wrp * 32 + mt * 16 + (lane & 15);
            int colh = kt * 16 + (lane >> 4) * 8;
            unsigned addr = (unsigned)__cvta_generic_to_shared(
                                &As[row * APITCH + colh]);
            unsigned a[4];
            asm volatile(
                "ldmatrix.sync.aligned.m8n8.x4.shared.b16 {%0,%1,%2,%3}, [%4];"
                : "=r"(a[0]), "=r"(a[1]), "=r"(a[2]), "=r"(a[3]) : "r"(addr));
            #pragma unroll
            for (int nt = 0; nt < 4; nt++)
                mma16816(acc[mt][nt], a, b[kt][nt][0], b[kt][nt][1]);
        }
    }

    // ---- PHASE D: relu + store ----
    #pragma unroll
    for (int mt = 0; mt < 2; mt++) {
        #pragma unroll
        for (int nt = 0; nt < 4; nt++) {
            int r0  = nbase + mt * 16 + g;
            int r1  = r0 + 8;
            int col = nt * 8 + tig * 2;
            float c0  = fmaxf(acc[mt][nt][0], 0.f);
            float c1  = fmaxf(acc[mt][nt][1], 0.f);
            float c2v = fmaxf(acc[mt][nt][2], 0.f);
            float c3v = fmaxf(acc[mt][nt][3], 0.f);
            if (OUT_HALF) {
                __half* out = reinterpret_cast<__half*>(outp);
                if (r0 < n)
                    *reinterpret_cast<__half2*>(out + (size_t)r0 * EMB + col)
                        = __floats2half2_rn(c0, c1);
                if (r1 < n)
                    *reinterpret_cast<__half2*>(out + (size_t)r1 * EMB + col)
                        = __floats2half2_rn(c2v, c3v);
            } else {
                float* out = reinterpret_cast<float*>(outp);
                if (r0 < n)
                    *reinterpret_cast<float2*>(out + (size_t)r0 * EMB + col)
                        = make_float2(c0, c1);
                if (r1 < n)
                    *reinterpret_cast<float2*>(out + (size_t)r1 * EMB + col)
                        = make_float2(c2v, c3v);
            }
        }
    }
}

extern "C" void kernel_launch(void* const* d_in, const int* in_sizes, int n_in,
                              void* d_out, int out_size)
{
    // metadata order: emb, W1, W2, node_batch, neigh
    const float* emb        = (const float*)d_in[0];
    const float* W1         = (const float*)d_in[1];
    const float* W2         = (const float*)d_in[2];
    const int*   node_batch = (const int*)  d_in[3];
    const int*   neigh      = (const int*)  d_in[4];
    float*       out        = (float*)d_out;

    const int N = in_sizes[0] / EMB;   // 500000
    const int B = in_sizes[3];         // 100000

    __half *embh = nullptr, *h1h = nullptr;
    cudaGetSymbolAddress((void**)&embh, g_embh);
    cudaGetSymbolAddress((void**)&h1h,  g_h1h);

    // emb fp32 -> fp16 (keeps gather working set L2-resident)
    cvt_f32_to_f16<<<8192, 256>>>((const float4*)emb, (uint4*)embh, N * EMB / 8);

    // Layer 1: h1 = relu([emb | mean(emb[neigh])] @ W1^T)  (fused, fp16 out)
    sage_fused_kernel<false, true><<<(N + 127) / 128, 128>>>(
        embh, nullptr, neigh, W1, h1h, N);

    // Layer 2: out = relu([h1[nb] | mean(h1[neigh[nb]])] @ W2^T)  (fused, fp32 out)
    sage_fused_kernel<true, false><<<(B + 127) / 128, 128>>>(
        h1h, node_batch, neigh, W2, out, B);
}

// round 13
// speedup vs baseline: 1.0516x; 1.0516x over previous
#include <cuda_runtime.h>
#include <cuda_fp16.h>

#define EMB 32
#define K 10
#define APITCH 72   // halves per A row (144B): ldmatrix conflict-free
#define WPITCH 72   // halves per Whs row

// fp16 tables (device globals: allocation-free scratch)
__device__ __align__(16) __half g_embh[500000 * EMB];   // 32 MB
__device__ __align__(16) __half g_h1h [500000 * EMB];   // 32 MB

// unpack 8 halves (one uint4) -> 8 floats
__device__ __forceinline__ void cvt8(uint4 v, float* f)
{
    const __half2* h = reinterpret_cast<const __half2*>(&v);
    #pragma unroll
    for (int i = 0; i < 4; i++) {
        float2 t = __half22float2(h[i]);
        f[2 * i]     = t.x;
        f[2 * i + 1] = t.y;
    }
}

// ---- fp32 -> fp16 conversion, 2 independent uint4 outputs per iter ----
__global__ __launch_bounds__(256)
void cvt_f32_to_f16(const float4* __restrict__ src, uint4* __restrict__ dst, int n8)
{
    int i = blockIdx.x * blockDim.x + threadIdx.x;
    int stride = gridDim.x * blockDim.x;
    for (; i + stride < n8; i += 2 * stride) {
        int j = i + stride;
        float4 a0 = src[2 * i],  b0 = src[2 * i + 1];
        float4 a1 = src[2 * j],  b1 = src[2 * j + 1];
        __half2 h0[4], h1[4];
        h0[0] = __floats2half2_rn(a0.x, a0.y); h0[1] = __floats2half2_rn(a0.z, a0.w);
        h0[2] = __floats2half2_rn(b0.x, b0.y); h0[3] = __floats2half2_rn(b0.z, b0.w);
        h1[0] = __floats2half2_rn(a1.x, a1.y); h1[1] = __floats2half2_rn(a1.z, a1.w);
        h1[2] = __floats2half2_rn(b1.x, b1.y); h1[3] = __floats2half2_rn(b1.z, b1.w);
        dst[i] = *reinterpret_cast<const uint4*>(h0);
        dst[j] = *reinterpret_cast<const uint4*>(h1);
    }
    for (; i < n8; i += stride) {
        float4 a = src[2 * i], b = src[2 * i + 1];
        __half2 h[4];
        h[0] = __floats2half2_rn(a.x, a.y); h[1] = __floats2half2_rn(a.z, a.w);
        h[2] = __floats2half2_rn(b.x, b.y); h[3] = __floats2half2_rn(b.z, b.w);
        dst[i] = *reinterpret_cast<const uint4*>(h);
    }
}

// ======================================================================
// FUSED layer kernel; W in smem (fp16), B-frags via ldmatrix (low regs)
// per warp D[32,32] = relu([self|agg(mean)] @ W^T) via HMMA m16n8k16
// ======================================================================
__device__ __forceinline__ void mma16816(float* c, const unsigned* a,
                                         unsigned b0, unsigned b1)
{
    asm volatile(
        "mma.sync.aligned.m16n8k16.row.col.f32.f16.f16.f32 "
        "{%0,%1,%2,%3}, {%4,%5,%6,%7}, {%8,%9}, {%0,%1,%2,%3};"
        : "+f"(c[0]), "+f"(c[1]), "+f"(c[2]), "+f"(c[3])
        : "r"(a[0]), "r"(a[1]), "r"(a[2]), "r"(a[3]), "r"(b0), "r"(b1));
}

__device__ __forceinline__ void ldsm_x4(unsigned* r, unsigned addr)
{
    asm volatile(
        "ldmatrix.sync.aligned.m8n8.x4.shared.b16 {%0,%1,%2,%3}, [%4];"
        : "=r"(r[0]), "=r"(r[1]), "=r"(r[2]), "=r"(r[3]) : "r"(addr));
}

template<bool SELF_GATHER, bool OUT_HALF>
__global__ __launch_bounds__(128, 7)
void sage_fused_kernel(const __half* __restrict__ feat,      // [*, 32] fp16
                       const int*    __restrict__ node_ids,  // if SELF_GATHER
                       const int*    __restrict__ neigh,     // [N_NODES, K]
                       const float*  __restrict__ W,         // [32 out, 64 in]
                       void*         __restrict__ outp,
                       int n)
{
    __shared__ __align__(16) __half As[128 * APITCH];   // 18.4 KB
    __shared__ __align__(16) __half Whs[32 * WPITCH];   // 4.6 KB  (row n, col k)

    const int tid   = threadIdx.x;
    const int lane  = tid & 31;
    const int wrp   = tid >> 5;
    const int g     = lane >> 2;      // group 0..7 (one node per pass)
    const int tig   = lane & 3;       // 16B chunk within 64B row
    const int nbase = blockIdx.x * 128 + wrp * 32;

    // ---- stage W (fp32 -> fp16) into smem, row n, k contiguous ----
    #pragma unroll
    for (int e = tid * 2; e < 32 * 64; e += 256) {
        int nr = e >> 6, kc = e & 63;
        __half2 h = __floats2half2_rn(W[e], W[e + 1]);
        *reinterpret_cast<__half2*>(&Whs[nr * WPITCH + kc]) = h;
    }
    __syncthreads();   // before any warp's mainloop; gathers come after (no convoy)

    // ---- PHASE A: gather self + mean(neigh) straight into As ----
    #pragma unroll
    for (int p = 0; p < 4; p++) {
        int r   = p * 8 + g;
        int row = wrp * 32 + r;
        int t   = nbase + r;
        int tc  = min(t, n - 1);
        int sid = SELF_GATHER ? node_ids[tc] : tc;

        uint4 vs = *(reinterpret_cast<const uint4*>(feat + (size_t)sid * EMB) + tig);

        int nb[K];                      // group-uniform loads (L1 broadcast)
        #pragma unroll
        for (int k = 0; k < K; k++)
            nb[k] = neigh[sid * K + k];

        uint4 raw[K];                   // 10 independent LDG.128 in flight
        #pragma unroll
        for (int k = 0; k < K; k++)
            raw[k] = *(reinterpret_cast<const uint4*>(feat + (size_t)nb[k] * EMB) + tig);

        float acc[8] = {0,0,0,0,0,0,0,0};
        #pragma unroll
        for (int k = 0; k < K; k++) {
            float f[8];
            cvt8(raw[k], f);
            #pragma unroll
            for (int i = 0; i < 8; i++) acc[i] += f[i];
        }

        __half2 h[4];
        #pragma unroll
        for (int i = 0; i < 4; i++)
            h[i] = __floats2half2_rn(acc[2 * i] * 0.1f, acc[2 * i + 1] * 0.1f);

        __half* dst = &As[row * APITCH];
        *reinterpret_cast<uint4*>(dst + tig * 8)      = vs;
        *reinterpret_cast<uint4*>(dst + 32 + tig * 8) = *reinterpret_cast<const uint4*>(h);
    }
    __syncwarp();

    // ---- PHASE B: mma mainloop; B-frags from smem per k-tile ----
    float acc[2][4][4];
    #pragma unroll
    for (int mt = 0; mt < 2; mt++)
        #pragma unroll
        for (int nt = 0; nt < 4; nt++)
            #pragma unroll
            for (int q = 0; q < 4; q++) acc[mt][nt][q] = 0.f;

    #pragma unroll
    for (int kt = 0; kt < 4; kt++) {
        // B fragments for all 4 n-tiles at this k-tile: 2 x ldmatrix.x4
        unsigned bfr[8];
        #pragma unroll
        for (int hgrp = 0; hgrp < 2; hgrp++) {
            int tl   = lane >> 3;            // tile index 0..3
            int rr   = lane & 7;             // row within tile
            int nrow = hgrp * 16 + (tl >> 1) * 8 + rr;
            int kcol = kt * 16 + (tl & 1) * 8;
            unsigned addr = (unsigned)__cvta_generic_to_shared(
                                &Whs[nrow * WPITCH + kcol]);
            ldsm_x4(&bfr[4 * hgrp], addr);
        }
        #pragma unroll
        for (int mt = 0; mt < 2; mt++) {
            int row  = wrp * 32 + mt * 16 + (lane & 15);
            int colh = kt * 16 + (lane >> 4) * 8;
            unsigned addr = (unsigned)__cvta_generic_to_shared(
                                &As[row * APITCH + colh]);
            unsigned a[4];
            ldsm_x4(a, addr);
            #pragma unroll
            for (int nt = 0; nt < 4; nt++)
                mma16816(acc[mt][nt], a, bfr[2 * nt], bfr[2 * nt + 1]);
        }
    }

    // ---- PHASE C: relu + store ----
    #pragma unroll
    for (int mt = 0; mt < 2; mt++) {
        #pragma unroll
        for (int nt = 0; nt < 4; nt++) {
            int r0  = nbase + mt * 16 + g;
            int r1  = r0 + 8;
            int col = nt * 8 + tig * 2;
            float c0  = fmaxf(acc[mt][nt][0], 0.f);
            float c1  = fmaxf(acc[mt][nt][1], 0.f);
            float c2v = fmaxf(acc[mt][nt][2], 0.f);
            float c3v = fmaxf(acc[mt][nt][3], 0.f);
            if (OUT_HALF) {
                __half* out = reinterpret_cast<__half*>(outp);
                if (r0 < n)
                    *reinterpret_cast<__half2*>(out + (size_t)r0 * EMB + col)
                        = __floats2half2_rn(c0, c1);
                if (r1 < n)
                    *reinterpret_cast<__half2*>(out + (size_t)r1 * EMB + col)
                        = __floats2half2_rn(c2v, c3v);
            } else {
                float* out = reinterpret_cast<float*>(outp);
                if (r0 < n)
                    *reinterpret_cast<float2*>(out + (size_t)r0 * EMB + col)
                        = make_float2(c0, c1);
                if (r1 < n)
                    *reinterpret_cast<float2*>(out + (size_t)r1 * EMB + col)
                        = make_float2(c2v, c3v);
            }
        }
    }
}

extern "C" void kernel_launch(void* const* d_in, const int* in_sizes, int n_in,
                              void* d_out, int out_size)
{
    // metadata order: emb, W1, W2, node_batch, neigh
    const float* emb        = (const float*)d_in[0];
    const float* W1         = (const float*)d_in[1];
    const float* W2         = (const float*)d_in[2];
    const int*   node_batch = (const int*)  d_in[3];
    const int*   neigh      = (const int*)  d_in[4];
    float*       out        = (float*)d_out;

    const int N = in_sizes[0] / EMB;   // 500000
    const int B = in_sizes[3];         // 100000

    __half *embh = nullptr, *h1h = nullptr;
    cudaGetSymbolAddress((void**)&embh, g_embh);
    cudaGetSymbolAddress((void**)&h1h,  g_h1h);

    // emb fp32 -> fp16 (keeps gather working set L2-resident)
    cvt_f32_to_f16<<<8192, 256>>>((const float4*)emb, (uint4*)embh, N * EMB / 8);

    // Layer 1: h1 = relu([emb | mean(emb[neigh])] @ W1^T)  (fused, fp16 out)
    sage_fused_kernel<false, true><<<(N + 127) / 128, 128>>>(
        embh, nullptr, neigh, W1, h1h, N);

    // Layer 2: out = relu([h1[nb] | mean(h1[neigh[nb]])] @ W2^T)  (fused, fp32 out)
    sage_fused_kernel<true, false><<<(B + 127) / 128, 128>>>(
        h1h, node_batch, neigh, W2, out, B);
}

// round 14
// speedup vs baseline: 1.1074x; 1.0531x over previous
#include <cuda_runtime.h>
#include <cuda_fp16.h>

#define EMB 32
#define K 10
#define APITCH 72   // halves per A row (144B): ldmatrix conflict-free
#define WPITCH 72   // halves per Whs row
#define NPB 64      // nodes per block (16 per warp)

// fp16 tables (device globals: allocation-free scratch)
__device__ __align__(16) __half g_embh[500000 * EMB];   // 32 MB
__device__ __align__(16) __half g_h1h [500000 * EMB];   // 32 MB

// unpack 8 halves (one uint4) -> 8 floats
__device__ __forceinline__ void cvt8(uint4 v, float* f)
{
    const __half2* h = reinterpret_cast<const __half2*>(&v);
    #pragma unroll
    for (int i = 0; i < 4; i++) {
        float2 t = __half22float2(h[i]);
        f[2 * i]     = t.x;
        f[2 * i + 1] = t.y;
    }
}

// ---- fp32 -> fp16 conversion, 2 independent uint4 outputs per iter ----
__global__ __launch_bounds__(256)
void cvt_f32_to_f16(const float4* __restrict__ src, uint4* __restrict__ dst, int n8)
{
    int i = blockIdx.x * blockDim.x + threadIdx.x;
    int stride = gridDim.x * blockDim.x;
    for (; i + stride < n8; i += 2 * stride) {
        int j = i + stride;
        float4 a0 = src[2 * i],  b0 = src[2 * i + 1];
        float4 a1 = src[2 * j],  b1 = src[2 * j + 1];
        __half2 h0[4], h1[4];
        h0[0] = __floats2half2_rn(a0.x, a0.y); h0[1] = __floats2half2_rn(a0.z, a0.w);
        h0[2] = __floats2half2_rn(b0.x, b0.y); h0[3] = __floats2half2_rn(b0.z, b0.w);
        h1[0] = __floats2half2_rn(a1.x, a1.y); h1[1] = __floats2half2_rn(a1.z, a1.w);
        h1[2] = __floats2half2_rn(b1.x, b1.y); h1[3] = __floats2half2_rn(b1.z, b1.w);
        dst[i] = *reinterpret_cast<const uint4*>(h0);
        dst[j] = *reinterpret_cast<const uint4*>(h1);
    }
    for (; i < n8; i += stride) {
        float4 a = src[2 * i], b = src[2 * i + 1];
        __half2 h[4];
        h[0] = __floats2half2_rn(a.x, a.y); h[1] = __floats2half2_rn(a.z, a.w);
        h[2] = __floats2half2_rn(b.x, b.y); h[3] = __floats2half2_rn(b.z, b.w);
        dst[i] = *reinterpret_cast<const uint4*>(h);
    }
}

// ======================================================================
// FUSED layer kernel: 16 nodes per warp, ids prefetched, W in smem.
// per warp D[16,32] = relu([self|agg(mean)] @ W^T) via HMMA m16n8k16
// ======================================================================
__device__ __forceinline__ void mma16816(float* c, const unsigned* a,
                                         unsigned b0, unsigned b1)
{
    asm volatile(
        "mma.sync.aligned.m16n8k16.row.col.f32.f16.f16.f32 "
        "{%0,%1,%2,%3}, {%4,%5,%6,%7}, {%8,%9}, {%0,%1,%2,%3};"
        : "+f"(c[0]), "+f"(c[1]), "+f"(c[2]), "+f"(c[3])
        : "r"(a[0]), "r"(a[1]), "r"(a[2]), "r"(a[3]), "r"(b0), "r"(b1));
}

__device__ __forceinline__ void ldsm_x4(unsigned* r, unsigned addr)
{
    asm volatile(
        "ldmatrix.sync.aligned.m8n8.x4.shared.b16 {%0,%1,%2,%3}, [%4];"
        : "=r"(r[0]), "=r"(r[1]), "=r"(r[2]), "=r"(r[3]) : "r"(addr));
}

template<bool SELF_GATHER, bool OUT_HALF>
__global__ __launch_bounds__(128, 7)
void sage_fused_kernel(const __half* __restrict__ feat,      // [*, 32] fp16
                       const int*    __restrict__ node_ids,  // if SELF_GATHER
                       const int*    __restrict__ neigh,     // [N_NODES, K]
                       const float*  __restrict__ W,         // [32 out, 64 in]
                       void*         __restrict__ outp,
                       int n)
{
    __shared__ __align__(16) __half As[NPB * APITCH];   // 9.2 KB
    __shared__ __align__(16) __half Whs[32 * WPITCH];   // 4.6 KB  (row n, col k)

    const int tid   = threadIdx.x;
    const int lane  = tid & 31;
    const int wrp   = tid >> 5;
    const int g     = lane >> 2;      // group 0..7 (one node per pass)
    const int tig   = lane & 3;       // 16B chunk within 64B row
    const int nbase = blockIdx.x * NPB + wrp * 16;

    // ---- stage W (fp32 -> fp16) into smem, row n, k contiguous ----
    #pragma unroll
    for (int e = tid * 2; e < 32 * 64; e += 256) {
        int nr = e >> 6, kc = e & 63;
        __half2 h = __floats2half2_rn(W[e], W[e + 1]);
        *reinterpret_cast<__half2*>(&Whs[nr * WPITCH + kc]) = h;
    }
    __syncthreads();   // before mainloop; gathers follow (no convoy)

    // ---- node ids + neighbor ids for BOTH passes (prefetched) ----
    int t0  = nbase + g,      t1 = nbase + 8 + g;
    int tc0 = min(t0, n - 1), tc1 = min(t1, n - 1);
    int sid0 = SELF_GATHER ? node_ids[tc0] : tc0;
    int sid1 = SELF_GATHER ? node_ids[tc1] : tc1;

    int nb0[K], nb1[K];      // group-uniform loads (L1 broadcast), all in flight
    #pragma unroll
    for (int k = 0; k < K; k++) nb0[k] = neigh[sid0 * K + k];
    #pragma unroll
    for (int k = 0; k < K; k++) nb1[k] = neigh[sid1 * K + k];

    // ---- PHASE A: gather pass 0 ----
    {
        uint4 vs = *(reinterpret_cast<const uint4*>(feat + (size_t)sid0 * EMB) + tig);
        uint4 raw[K];
        #pragma unroll
        for (int k = 0; k < K; k++)
            raw[k] = *(reinterpret_cast<const uint4*>(feat + (size_t)nb0[k] * EMB) + tig);
        float acc[8] = {0,0,0,0,0,0,0,0};
        #pragma unroll
        for (int k = 0; k < K; k++) {
            float f[8]; cvt8(raw[k], f);
            #pragma unroll
            for (int i = 0; i < 8; i++) acc[i] += f[i];
        }
        __half2 h[4];
        #pragma unroll
        for (int i = 0; i < 4; i++)
            h[i] = __floats2half2_rn(acc[2 * i] * 0.1f, acc[2 * i + 1] * 0.1f);
        __half* dst = &As[(wrp * 16 + g) * APITCH];
        *reinterpret_cast<uint4*>(dst + tig * 8)      = vs;
        *reinterpret_cast<uint4*>(dst + 32 + tig * 8) = *reinterpret_cast<const uint4*>(h);
    }
    // ---- gather pass 1 (ids already resident) ----
    {
        uint4 vs = *(reinterpret_cast<const uint4*>(feat + (size_t)sid1 * EMB) + tig);
        uint4 raw[K];
        #pragma unroll
        for (int k = 0; k < K; k++)
            raw[k] = *(reinterpret_cast<const uint4*>(feat + (size_t)nb1[k] * EMB) + tig);
        float acc[8] = {0,0,0,0,0,0,0,0};
        #pragma unroll
        for (int k = 0; k < K; k++) {
            float f[8]; cvt8(raw[k], f);
            #pragma unroll
            for (int i = 0; i < 8; i++) acc[i] += f[i];
        }
        __half2 h[4];
        #pragma unroll
        for (int i = 0; i < 4; i++)
            h[i] = __floats2half2_rn(acc[2 * i] * 0.1f, acc[2 * i + 1] * 0.1f);
        __half* dst = &As[(wrp * 16 + 8 + g) * APITCH];
        *reinterpret_cast<uint4*>(dst + tig * 8)      = vs;
        *reinterpret_cast<uint4*>(dst + 32 + tig * 8) = *reinterpret_cast<const uint4*>(h);
    }
    __syncwarp();

    // ---- PHASE B: mma mainloop (1 m-tile x 4 n-tiles x 4 k-tiles) ----
    float acc[4][4];
    #pragma unroll
    for (int nt = 0; nt < 4; nt++)
        #pragma unroll
        for (int q = 0; q < 4; q++) acc[nt][q] = 0.f;

    #pragma unroll
    for (int kt = 0; kt < 4; kt++) {
        // B fragments for all 4 n-tiles at this k-tile: 2 x ldmatrix.x4
        unsigned bfr[8];
        #pragma unroll
        for (int hgrp = 0; hgrp < 2; hgrp++) {
            int tl   = lane >> 3;
            int rr   = lane & 7;
            int nrow = hgrp * 16 + (tl >> 1) * 8 + rr;
            int kcol = kt * 16 + (tl & 1) * 8;
            unsigned addr = (unsigned)__cvta_generic_to_shared(
                                &Whs[nrow * WPITCH + kcol]);
            ldsm_x4(&bfr[4 * hgrp], addr);
        }
        int row  = wrp * 16 + (lane & 15);
        int colh = kt * 16 + (lane >> 4) * 8;
        unsigned addr = (unsigned)__cvta_generic_to_shared(
                            &As[row * APITCH + colh]);
        unsigned a[4];
        ldsm_x4(a, addr);
        #pragma unroll
        for (int nt = 0; nt < 4; nt++)
            mma16816(acc[nt], a, bfr[2 * nt], bfr[2 * nt + 1]);
    }

    // ---- PHASE C: relu + store ----
    #pragma unroll
    for (int nt = 0; nt < 4; nt++) {
        int r0  = nbase + g;
        int r1  = r0 + 8;
        int col = nt * 8 + tig * 2;
        float c0  = fmaxf(acc[nt][0], 0.f);
        float c1  = fmaxf(acc[nt][1], 0.f);
        float c2v = fmaxf(acc[nt][2], 0.f);
        float c3v = fmaxf(acc[nt][3], 0.f);
        if (OUT_HALF) {
            __half* out = reinterpret_cast<__half*>(outp);
            if (r0 < n)
                *reinterpret_cast<__half2*>(out + (size_t)r0 * EMB + col)
                    = __floats2half2_rn(c0, c1);
            if (r1 < n)
                *reinterpret_cast<__half2*>(out + (size_t)r1 * EMB + col)
                    = __floats2half2_rn(c2v, c3v);
        } else {
            float* out = reinterpret_cast<float*>(outp);
            if (r0 < n)
                *reinterpret_cast<float2*>(out + (size_t)r0 * EMB + col)
                    = make_float2(c0, c1);
            if (r1 < n)
                *reinterpret_cast<float2*>(out + (size_t)r1 * EMB + col)
                    = make_float2(c2v, c3v);
        }
    }
}

extern "C" void kernel_launch(void* const* d_in, const int* in_sizes, int n_in,
                              void* d_out, int out_size)
{
    // metadata order: emb, W1, W2, node_batch, neigh
    const float* emb        = (const float*)d_in[0];
    const float* W1         = (const float*)d_in[1];
    const float* W2         = (const float*)d_in[2];
    const int*   node_batch = (const int*)  d_in[3];
    const int*   neigh      = (const int*)  d_in[4];
    float*       out        = (float*)d_out;

    const int N = in_sizes[0] / EMB;   // 500000
    const int B = in_sizes[3];         // 100000

    __half *embh = nullptr, *h1h = nullptr;
    cudaGetSymbolAddress((void**)&embh, g_embh);
    cudaGetSymbolAddress((void**)&h1h,  g_h1h);

    // emb fp32 -> fp16 (keeps gather working set L2-resident)
    cvt_f32_to_f16<<<8192, 256>>>((const float4*)emb, (uint4*)embh, N * EMB / 8);

    // Layer 1: h1 = relu([emb | mean(emb[neigh])] @ W1^T)  (fused, fp16 out)
    sage_fused_kernel<false, true><<<(N + NPB - 1) / NPB, 128>>>(
        embh, nullptr, neigh, W1, h1h, N);

    // Layer 2: out = relu([h1[nb] | mean(h1[neigh[nb]])] @ W2^T)  (fused, fp32 out)
    sage_fused_kernel<true, false><<<(B + NPB - 1) / NPB, 128>>>(
        h1h, node_batch, neigh, W2, out, B);
}